// round 3
// baseline (speedup 1.0000x reference)
#include <cuda_runtime.h>
#include <cstdint>

// TaylorExp: x [4,16,4096,16] f32 -> out [4,16,4096,273] f32
// out_row = [1, 0.5*x, vec(x x^T) / (4*sqrt(2))]
//
// R3: compute into a shared staging buffer, then one cp.async.bulk (TMA bulk
// store) per block writes the block's contiguous 34944-byte output slice.
// Removes the STG->L1tex store path entirely; DRAM sees large bulk writes.

#define WARPS_PER_BLOCK 8
#define THREADS (WARPS_PER_BLOCK * 32)

static constexpr int TOTAL_ROWS  = 4 * 16 * 4096;   // 262144
static constexpr int GROUPS      = TOTAL_ROWS / 4;  // 65536 (4 rows per warp)
static constexpr int VEC_PER_GRP = 273;             // float4 per group
static constexpr int BLOCK_BYTES = WARPS_PER_BLOCK * VEC_PER_GRP * 16; // 34944

__device__ __forceinline__ float lds_f32(unsigned addr) {
    float v;
    asm volatile("ld.shared.f32 %0, [%1];" : "=f"(v) : "r"(addr));
    return v;
}

__global__ __launch_bounds__(THREADS)
void TaylorExp_14783277432863_kernel(const float* __restrict__ x,
                                     float* __restrict__ out) {
    __shared__ uint4 tab[273];                             // 4368 B
    __shared__ float pq[WARPS_PER_BLOCK][136];             // 4352 B
    __shared__ alignas(16) float4 obuf[WARPS_PER_BLOCK][VEC_PER_GRP]; // 34944 B

    const int tid  = threadIdx.x;
    const int warp = tid >> 5;
    const int lane = tid & 31;
    const int group = blockIdx.x * WARPS_PER_BLOCK + warp;   // grid exact

    // ---- build offset table (identical for all groups) ----
    for (int k = tid; k < 273; k += THREADS) {
        unsigned w[4];
        #pragma unroll
        for (int c = 0; c < 4; ++c) {
            const int ec  = 4 * k + c;
            const int row = (ec >= 273) + (ec >= 546) + (ec >= 819);
            const int f   = ec - row * 273;
            int ia, ib;                 // float indices into pq[warp][136]
            if (f == 0)       { ia = row * 17;          ib = 68 + row * 17; }
            else if (f <= 16) { ia = row * 17 + f;      ib = 68 + row * 17; }
            else {
                const int q = f - 17;
                ia = row * 17 + 1 + (q >> 4);
                ib = 68 + row * 17 + 1 + (q & 15);
            }
            w[c] = (unsigned)(ia * 4) | ((unsigned)(ib * 4) << 16);  // byte offs
        }
        tab[k] = make_uint4(w[0], w[1], w[2], w[3]);
    }

    // ---- fill per-warp P/Q (pre-scaled inputs) ----
    const float4* xg = reinterpret_cast<const float4*>(x) + (size_t)group * 16;
    if (lane < 16) {
        float4 v = __ldg(&xg[lane]);
        const int row = lane >> 2, part = lane & 3;
        float* P = pq[warp];
        float* Q = pq[warp] + 68;
        const int bi = row * 17 + 1 + part * 4;
        P[bi + 0] = 0.5f * v.x;  P[bi + 1] = 0.5f * v.y;
        P[bi + 2] = 0.5f * v.z;  P[bi + 3] = 0.5f * v.w;
        const float c2 = 0.5f * 0.70710678118654752f;
        Q[bi + 0] = c2 * v.x;    Q[bi + 1] = c2 * v.y;
        Q[bi + 2] = c2 * v.z;    Q[bi + 3] = c2 * v.w;
    }
    if (lane < 4) {                          // unit entries for const/linear
        pq[warp][lane * 17]      = 1.0f;
        pq[warp][68 + lane * 17] = 1.0f;
    }
    __syncthreads();

    const unsigned sb = (unsigned)__cvta_generic_to_shared(&pq[warp][0]);
    float4* ob = obuf[warp];

    #pragma unroll
    for (int it = 0; it < 9; ++it) {
        const int k = lane + it * 32;
        if (it < 8 || k < VEC_PER_GRP) {     // 273 = 8*32 + 17
            const uint4 cd = tab[k];
            float4 v;
            v.x = lds_f32(sb + (cd.x & 0xFFFFu)) * lds_f32(sb + (cd.x >> 16));
            v.y = lds_f32(sb + (cd.y & 0xFFFFu)) * lds_f32(sb + (cd.y >> 16));
            v.z = lds_f32(sb + (cd.z & 0xFFFFu)) * lds_f32(sb + (cd.z >> 16));
            v.w = lds_f32(sb + (cd.w & 0xFFFFu)) * lds_f32(sb + (cd.w >> 16));
            ob[k] = v;                       // STS.128, conflict-free
        }
    }

    __syncthreads();
    // Order generic-proxy STS before async-proxy (TMA) reads of smem.
    asm volatile("fence.proxy.async.shared::cta;" ::: "memory");

    if (tid == 0) {
        const unsigned src =
            (unsigned)__cvta_generic_to_shared(&obuf[0][0]);
        char* dst = reinterpret_cast<char*>(out) +
                    (size_t)blockIdx.x * BLOCK_BYTES;
        asm volatile(
            "cp.async.bulk.global.shared::cta.bulk_group [%0], [%1], %2;"
            :: "l"(dst), "r"(src), "r"((unsigned)BLOCK_BYTES) : "memory");
        asm volatile("cp.async.bulk.commit_group;" ::: "memory");
        asm volatile("cp.async.bulk.wait_group 0;" ::: "memory");
    }
}

extern "C" void kernel_launch(void* const* d_in, const int* in_sizes, int n_in,
                              void* d_out, int out_size) {
    const float* x = (const float*)d_in[0];
    float* out = (float*)d_out;
    (void)in_sizes; (void)n_in; (void)out_size;

    const int blocks = GROUPS / WARPS_PER_BLOCK;   // 8192
    TaylorExp_14783277432863_kernel<<<blocks, THREADS>>>(x, out);
}

// round 4
// speedup vs baseline: 1.2086x; 1.2086x over previous
#include <cuda_runtime.h>
#include <cstdint>

// TaylorExp: x [4,16,4096,16] f32 -> out [4,16,4096,273] f32
// out_row = [1, 0.5*x, vec(x x^T) / (4*sqrt(2))]
//
// R4: R2 table-driven kernel with ONE change: output stores use the
// evict-first streaming hint (st.global.cs.v4 via __stcs) so L2 dirty
// lines drain to DRAM eagerly instead of waiting for capacity eviction.

#define WARPS_PER_BLOCK 8
#define THREADS (WARPS_PER_BLOCK * 32)

static constexpr int TOTAL_ROWS  = 4 * 16 * 4096;   // 262144
static constexpr int GROUPS      = TOTAL_ROWS / 4;  // 65536 (4 rows per warp)
static constexpr int VEC_PER_GRP = 273;             // float4 per group

__device__ __forceinline__ float lds_f32(unsigned addr) {
    float v;
    asm volatile("ld.shared.f32 %0, [%1];" : "=f"(v) : "r"(addr));
    return v;
}

__device__ __forceinline__ void stg_cs_v4(float4* p, float4 v) {
    asm volatile("st.global.cs.v4.f32 [%0], {%1, %2, %3, %4};"
                 :: "l"(p), "f"(v.x), "f"(v.y), "f"(v.z), "f"(v.w)
                 : "memory");
}

__global__ __launch_bounds__(THREADS)
void TaylorExp_14783277432863_kernel(const float* __restrict__ x,
                                     float* __restrict__ out) {
    __shared__ uint4 tab[273];                     // 4368 B, block-shared
    __shared__ float pq[WARPS_PER_BLOCK][136];     // P[68] | Q[68] per warp

    const int tid  = threadIdx.x;
    const int warp = tid >> 5;
    const int lane = tid & 31;
    const int group = blockIdx.x * WARPS_PER_BLOCK + warp;   // grid exact

    // ---- build offset table (identical for all groups) ----
    for (int k = tid; k < 273; k += THREADS) {
        unsigned w[4];
        #pragma unroll
        for (int c = 0; c < 4; ++c) {
            const int ec  = 4 * k + c;
            const int row = (ec >= 273) + (ec >= 546) + (ec >= 819);
            const int f   = ec - row * 273;
            int ia, ib;                 // float indices into pq[warp][136]
            if (f == 0)       { ia = row * 17;          ib = 68 + row * 17; }
            else if (f <= 16) { ia = row * 17 + f;      ib = 68 + row * 17; }
            else {
                const int q = f - 17;
                ia = row * 17 + 1 + (q >> 4);
                ib = 68 + row * 17 + 1 + (q & 15);
            }
            w[c] = (unsigned)(ia * 4) | ((unsigned)(ib * 4) << 16);  // byte offs
        }
        tab[k] = make_uint4(w[0], w[1], w[2], w[3]);
    }

    // ---- fill per-warp P/Q (pre-scaled inputs) ----
    const float4* xg = reinterpret_cast<const float4*>(x) + (size_t)group * 16;
    if (lane < 16) {
        float4 v = __ldg(&xg[lane]);
        const int row = lane >> 2, part = lane & 3;
        float* P = pq[warp];
        float* Q = pq[warp] + 68;
        const int bi = row * 17 + 1 + part * 4;
        P[bi + 0] = 0.5f * v.x;  P[bi + 1] = 0.5f * v.y;
        P[bi + 2] = 0.5f * v.z;  P[bi + 3] = 0.5f * v.w;
        const float c2 = 0.5f * 0.70710678118654752f;
        Q[bi + 0] = c2 * v.x;    Q[bi + 1] = c2 * v.y;
        Q[bi + 2] = c2 * v.z;    Q[bi + 3] = c2 * v.w;
    }
    if (lane < 4) {                          // unit entries for const/linear
        pq[warp][lane * 17]      = 1.0f;
        pq[warp][68 + lane * 17] = 1.0f;
    }
    __syncthreads();

    const unsigned sb = (unsigned)__cvta_generic_to_shared(&pq[warp][0]);
    float4* og = reinterpret_cast<float4*>(out) + (size_t)group * VEC_PER_GRP;

    #pragma unroll
    for (int it = 0; it < 9; ++it) {
        const int k = lane + it * 32;
        if (it < 8 || k < VEC_PER_GRP) {     // 273 = 8*32 + 17
            const uint4 cd = tab[k];
            float4 v;
            v.x = lds_f32(sb + (cd.x & 0xFFFFu)) * lds_f32(sb + (cd.x >> 16));
            v.y = lds_f32(sb + (cd.y & 0xFFFFu)) * lds_f32(sb + (cd.y >> 16));
            v.z = lds_f32(sb + (cd.z & 0xFFFFu)) * lds_f32(sb + (cd.z >> 16));
            v.w = lds_f32(sb + (cd.w & 0xFFFFu)) * lds_f32(sb + (cd.w >> 16));
            stg_cs_v4(og + k, v);            // evict-first streaming store
        }
    }
}

extern "C" void kernel_launch(void* const* d_in, const int* in_sizes, int n_in,
                              void* d_out, int out_size) {
    const float* x = (const float*)d_in[0];
    float* out = (float*)d_out;
    (void)in_sizes; (void)n_in; (void)out_size;

    const int blocks = GROUPS / WARPS_PER_BLOCK;   // 8192
    TaylorExp_14783277432863_kernel<<<blocks, THREADS>>>(x, out);
}